// round 2
// baseline (speedup 1.0000x reference)
#include <cuda_runtime.h>
#include <cstdint>

#define NBLK   128
#define NTHR   256
#define TSTEPS 512
#define OUTN   (512*128*512)

// -------- persistent state (device globals; no allocation allowed) ----------
__device__ __align__(16) float g_h[2][2][128*512];   // [layer][pingpong][n*512+j]
__device__ unsigned g_bar_count = 0;
__device__ volatile unsigned g_bar_gen = 0;

// -------- software grid barrier (all 128 CTAs co-resident) ------------------
__device__ __forceinline__ void grid_barrier() {
    __syncthreads();
    if (threadIdx.x == 0) {
        __threadfence();
        unsigned gen = g_bar_gen;
        if (atomicAdd(&g_bar_count, 1u) == NBLK - 1) {
            g_bar_count = 0;
            __threadfence();
            g_bar_gen = gen + 1;
        } else {
            while (g_bar_gen == gen) { __nanosleep(20); }
        }
        __threadfence();
    }
    __syncthreads();
}

// -------- cp.async helpers (cg = L2-only, keeps cross-CTA h coherent) -------
__device__ __forceinline__ void cp16(void* s, const void* g) {
    uint32_t sa = (uint32_t)__cvta_generic_to_shared(s);
    asm volatile("cp.async.cg.shared.global [%0], [%1], 16;" :: "r"(sa), "l"(g));
}
__device__ __forceinline__ void cp_commit() { asm volatile("cp.async.commit_group;"); }
template<int N> __device__ __forceinline__ void cp_wait() {
    asm volatile("cp.async.wait_group %0;" :: "n"(N));
}

// Stage one 128n x 64k tile (row stride 68 floats: 16B aligned, 4-phase
// conflict-free LDS). src points at (row base + k-offset); rows stride 512.
__device__ __forceinline__ void stage_tile(float* buf, const float* __restrict__ src) {
    int tid = threadIdx.x;
#pragma unroll
    for (int r = 0; r < 8; ++r) {
        int s  = tid + (r << 8);      // 0..2047 float4 slots
        int n  = s >> 4;              // 0..127
        int kq = s & 15;              // float4 within row
        cp16(buf + n * 68 + (kq << 2), src + n * 512 + (kq << 2));
    }
}

// 64-k GEMM tile: thread tile = 4 n (strided) x 2 cols. Weight LDS are
// warp-uniform (broadcast, ~free); input LDS conflict-free.
__device__ __forceinline__ void gemm_tile(const float* __restrict__ buf,
                                          const float* __restrict__ wa,
                                          const float* __restrict__ wb,
                                          float (&acc)[4][2]) {
    int ng = threadIdx.x & 31;
#pragma unroll
    for (int kk = 0; kk < 16; ++kk) {
        float4 w0 = ((const float4*)wa)[kk];
        float4 w1 = ((const float4*)wb)[kk];
#pragma unroll
        for (int i = 0; i < 4; ++i) {
            float4 a = *(const float4*)(buf + (ng + (i << 5)) * 68 + (kk << 2));
            acc[i][0] = fmaf(a.x, w0.x, acc[i][0]);
            acc[i][0] = fmaf(a.y, w0.y, acc[i][0]);
            acc[i][0] = fmaf(a.z, w0.z, acc[i][0]);
            acc[i][0] = fmaf(a.w, w0.w, acc[i][0]);
            acc[i][1] = fmaf(a.x, w1.x, acc[i][1]);
            acc[i][1] = fmaf(a.y, w1.y, acc[i][1]);
            acc[i][1] = fmaf(a.z, w1.z, acc[i][1]);
            acc[i][1] = fmaf(a.w, w1.w, acc[i][1]);
        }
    }
}

__device__ __forceinline__ float sigm(float x) { return 1.0f / (1.0f + __expf(-x)); }

// One layer phase: z = inp@Wih^T + (m*h)@Whh^T + b; gates; write h_new.
// Tiles 0-7 = inp region (unmasked, acc0); tiles 8-15 = h-state (masked, acc1).
__device__ __forceinline__ void lstm_phase(
    int l, int t,
    const float* __restrict__ s0,       // inp rows   (+ n*512 + k)
    const float* __restrict__ s1,       // h-state rows
    float* __restrict__ hdst,           // h_new (stcg)
    float* __restrict__ outdst,         // layer-1: out[t] slab, else nullptr
    float* __restrict__ outbase,        // d_out base (final hxs writes)
    const float* __restrict__ masks,
    const float* Wsh, const float* bsh, float* tile0, float* tile1, float* zsh,
    float (&c_reg)[2], int blk)
{
    int tid = threadIdx.x;
    int ng = tid & 31, cg = tid >> 5;               // warp == cg
    const float* w0b = Wsh + (l * 16 + cg * 2) * 1024;
    const float* w1b = w0b + 1024;

    float acc0[4][2] = {}, acc1[4][2] = {};

    stage_tile(tile0, s0);
    cp_commit();
#pragma unroll 1
    for (int it = 0; it < 16; ++it) {
        if (it < 15) {
            int kt = (it + 1) << 6;
            const float* src = (kt < 512) ? (s0 + kt) : (s1 + (kt - 512));
            stage_tile((it & 1) ? tile0 : tile1, src);
            cp_commit();
            cp_wait<1>();
        } else {
            cp_wait<0>();
        }
        __syncthreads();
        const float* buf = (it & 1) ? tile1 : tile0;
        const float* wa = w0b + (it << 6);
        const float* wb = w1b + (it << 6);
        if (it < 8) gemm_tile(buf, wa, wb, acc0);
        else        gemm_tile(buf, wa, wb, acc1);
        __syncthreads();
    }

    // z writeback: mask scales ONLY the h-state partial sum
    float b0 = bsh[l * 16 + cg * 2];
    float b1 = bsh[l * 16 + cg * 2 + 1];
#pragma unroll
    for (int i = 0; i < 4; ++i) {
        int n = ng + (i << 5);
        float m = __ldg(masks + t * 128 + n);
        zsh[(cg * 2) * 128 + n]     = acc0[i][0] + m * acc1[i][0] + b0;
        zsh[(cg * 2 + 1) * 128 + n] = acc0[i][1] + m * acc1[i][1] + b1;
    }
    __syncthreads();

    // gate stage: thread owns 2 (n,u) cells; c stays in registers
    int n = tid & 127;
    float m = __ldg(masks + t * 128 + n);
#pragma unroll
    for (int j = 0; j < 2; ++j) {
        int u = (tid >> 7) + (j << 1);              // 0..3
        float zi = zsh[(0  + u) * 128 + n];
        float zf = zsh[(4  + u) * 128 + n];
        float zg = zsh[(8  + u) * 128 + n];
        float zo = zsh[(12 + u) * 128 + n];
        float ii = sigm(zi), ff = sigm(zf), oo = sigm(zo);
        float gg = tanhf(zg);
        float cc = ff * (c_reg[j] * m) + ii * gg;
        float hh = oo * tanhf(cc);
        c_reg[j] = cc;
        int ug = blk * 4 + u;
        __stcg(hdst + n * 512 + ug, hh);
        if (outdst) outdst[n * 512 + ug] = hh;
        if (t == TSTEPS - 1) {
            outbase[OUTN + l * 131072 + n * 1024 + ug]       = hh;  // hT
            outbase[OUTN + l * 131072 + n * 1024 + 512 + ug] = cc;  // cT
        }
    }
}

__global__ void __launch_bounds__(NTHR, 1) lstm_persistent(
    const float* __restrict__ x, const float* __restrict__ hxs,
    const float* __restrict__ masks,
    const float* __restrict__ W_ih, const float* __restrict__ W_hh,
    const float* __restrict__ b_ih, const float* __restrict__ b_hh,
    float* __restrict__ out)
{
    extern __shared__ float sm[];
    float* Wsh   = sm;                  // 2*16*1024 = 32768 floats
    float* tile0 = Wsh + 32768;         // 128*68 = 8704
    float* tile1 = tile0 + 8704;
    float* zsh   = tile1 + 8704;        // 16*128 = 2048
    float* bsh   = zsh + 2048;          // 32

    int blk = blockIdx.x, tid = threadIdx.x;

    // --- load this CTA's weight rows: Wsh[l][c][0:512]=W_ih row, [512:1024]=W_hh
    for (int q = tid; q < 8192; q += NTHR) {
        int f  = q << 2;
        int lc = f >> 10;               // l*16 + c
        int k  = f & 1023;
        int l  = lc >> 4, c = lc & 15;
        int row = (c >> 2) * 512 + blk * 4 + (c & 3);   // gate*512 + unit
        const float* srcw = (k < 512)
            ? (W_ih + ((l * 2048 + row) << 9) + k)
            : (W_hh + ((l * 2048 + row) << 9) + (k - 512));
        *(float4*)(Wsh + f) = *(const float4*)srcw;
    }
    if (tid < 32) {
        int l = tid >> 4, c = tid & 15;
        int row = (c >> 2) * 512 + blk * 4 + (c & 3);
        bsh[tid] = b_ih[l * 2048 + row] + b_hh[l * 2048 + row];
    }

    // --- init h state (buffer 0) from hxs, grid-strided
    for (int idx = blk * NTHR + tid; idx < 2 * 128 * 512; idx += NBLK * NTHR) {
        int l = idx >> 16, r = idx & 65535;
        int n = r >> 9, jj = r & 511;
        __stcg(&g_h[l][0][r], hxs[l * 131072 + n * 1024 + jj]);
    }

    // --- init c (registers)
    float c_reg[2][2];
    {
        int n = tid & 127;
#pragma unroll
        for (int l = 0; l < 2; ++l)
#pragma unroll
            for (int j = 0; j < 2; ++j) {
                int u = (tid >> 7) + (j << 1);
                c_reg[l][j] = hxs[l * 131072 + n * 1024 + 512 + blk * 4 + u];
            }
    }
    __syncthreads();
    grid_barrier();

#pragma unroll 1
    for (int t = 0; t < TSTEPS; ++t) {
        int pr = t & 1, pw = pr ^ 1;
        // layer 0: inp = x_t (unmasked), state = h0[pr] (masked)
        lstm_phase(0, t, x + t * 65536, g_h[0][pr],
                   g_h[0][pw], nullptr, out, masks,
                   Wsh, bsh, tile0, tile1, zsh, c_reg[0], blk);
        grid_barrier();
        // layer 1: inp = h0_new (unmasked), state = h1[pr] (masked)
        lstm_phase(1, t, g_h[0][pw], g_h[1][pr],
                   g_h[1][pw], out + t * 65536, out, masks,
                   Wsh, bsh, tile0, tile1, zsh, c_reg[1], blk);
    }
}

// -------- LayerNorm over out rows (warp per row, in-place) ------------------
__global__ void __launch_bounds__(256) ln_kernel(float* __restrict__ out,
                                                 const float* __restrict__ gamma,
                                                 const float* __restrict__ beta)
{
    int lane = threadIdx.x & 31;
    int row  = blockIdx.x * 8 + (threadIdx.x >> 5);   // 0..65535
    float* p = out + (size_t)row * 512;

    float4 v[4];
    float s = 0.f, sq = 0.f;
#pragma unroll
    for (int k = 0; k < 4; ++k) {
        v[k] = ((const float4*)p)[(k << 5) + lane];
        s += v[k].x + v[k].y + v[k].z + v[k].w;
        sq = fmaf(v[k].x, v[k].x, sq);
        sq = fmaf(v[k].y, v[k].y, sq);
        sq = fmaf(v[k].z, v[k].z, sq);
        sq = fmaf(v[k].w, v[k].w, sq);
    }
#pragma unroll
    for (int o = 16; o; o >>= 1) {
        s  += __shfl_xor_sync(0xffffffffu, s,  o);
        sq += __shfl_xor_sync(0xffffffffu, sq, o);
    }
    float mean = s * (1.0f / 512.0f);
    float inv  = rsqrtf(sq * (1.0f / 512.0f) - mean * mean + 1e-5f);
#pragma unroll
    for (int k = 0; k < 4; ++k) {
        float4 g = ((const float4*)gamma)[(k << 5) + lane];
        float4 b = ((const float4*)beta)[(k << 5) + lane];
        float4 r;
        r.x = (v[k].x - mean) * inv * g.x + b.x;
        r.y = (v[k].y - mean) * inv * g.y + b.y;
        r.z = (v[k].z - mean) * inv * g.z + b.z;
        r.w = (v[k].w - mean) * inv * g.w + b.w;
        ((float4*)p)[(k << 5) + lane] = r;
    }
}

// ---------------------------------------------------------------------------
extern "C" void kernel_launch(void* const* d_in, const int* in_sizes, int n_in,
                              void* d_out, int out_size) {
    const float* x     = (const float*)d_in[0];
    const float* hxs   = (const float*)d_in[1];
    const float* masks = (const float*)d_in[2];
    const float* W_ih  = (const float*)d_in[3];
    const float* W_hh  = (const float*)d_in[4];
    const float* b_ih  = (const float*)d_in[5];
    const float* b_hh  = (const float*)d_in[6];
    const float* gamma = (const float*)d_in[7];
    const float* beta  = (const float*)d_in[8];
    float* out = (float*)d_out;

    const int SMEM_BYTES = (32768 + 8704 + 8704 + 2048 + 32) * 4;  // 209024
    cudaFuncSetAttribute(lstm_persistent,
                         cudaFuncAttributeMaxDynamicSharedMemorySize, SMEM_BYTES);

    lstm_persistent<<<NBLK, NTHR, SMEM_BYTES>>>(x, hxs, masks, W_ih, W_hh,
                                                b_ih, b_hh, out);
    ln_kernel<<<65536 / 8, 256>>>(out, gamma, beta);
}

// round 4
// speedup vs baseline: 2.8582x; 2.8582x over previous
#include <cuda_runtime.h>
#include <cuda_bf16.h>
#include <cstdint>

#define NBLK   128
#define NTHR   128
#define TSTEPS 512
#define OUTN   (512*128*512)

// ---- smem byte offsets -----------------------------------------------------
#define SM_BIAS 0         // 32 f32
#define SM_ZSH  128       // 16*132*4 = 8448
#define SM_W    8576      // B fragments: 2l*2half*64ks*2nt*32lane*8B = 131072
#define SM_A    139648    // 2 bufs * (hi 16KB + lo 16KB) = 65536
#define SM_TOT  205184

// ---- persistent state ------------------------------------------------------
__device__ __align__(16) __nv_bfloat16 g_x_hi[(size_t)TSTEPS*128*512];
__device__ __align__(16) __nv_bfloat16 g_x_lo[(size_t)TSTEPS*128*512];
__device__ __align__(16) __nv_bfloat16 g_hst[2][2][2][128*512]; // [layer][pp][half]
__device__ __align__(16) __nv_bfloat16 g_mid[2][2][128*512];    // [pp][half]
__device__ unsigned g_bar_count = 0;
__device__ volatile unsigned g_bar_gen = 0;

// ---- grid barrier ----------------------------------------------------------
__device__ __forceinline__ void grid_barrier() {
    __syncthreads();
    if (threadIdx.x == 0) {
        __threadfence();
        unsigned gen = g_bar_gen;
        if (atomicAdd(&g_bar_count, 1u) == NBLK - 1) {
            g_bar_count = 0;
            __threadfence();
            g_bar_gen = gen + 1;
        } else {
            while (g_bar_gen == gen) { __nanosleep(20); }
        }
        __threadfence();
    }
    __syncthreads();
}

// ---- asm helpers -----------------------------------------------------------
__device__ __forceinline__ void cp16(uint32_t s, const void* g) {
    asm volatile("cp.async.cg.shared.global [%0], [%1], 16;" :: "r"(s), "l"(g));
}
__device__ __forceinline__ void cp_commit() { asm volatile("cp.async.commit_group;"); }
template<int N> __device__ __forceinline__ void cp_wait() {
    asm volatile("cp.async.wait_group %0;" :: "n"(N));
}
__device__ __forceinline__ void ldm4(uint32_t (&a)[4], uint32_t addr) {
    asm volatile("ldmatrix.sync.aligned.m8n8.x4.shared.b16 {%0,%1,%2,%3}, [%4];"
                 : "=r"(a[0]), "=r"(a[1]), "=r"(a[2]), "=r"(a[3]) : "r"(addr));
}
__device__ __forceinline__ void mma(float (&d)[4], const uint32_t (&a)[4],
                                    uint32_t b0, uint32_t b1) {
    asm volatile("mma.sync.aligned.m16n8k16.row.col.f32.bf16.bf16.f32 "
        "{%0,%1,%2,%3}, {%4,%5,%6,%7}, {%8,%9}, {%0,%1,%2,%3};"
        : "+f"(d[0]), "+f"(d[1]), "+f"(d[2]), "+f"(d[3])
        : "r"(a[0]), "r"(a[1]), "r"(a[2]), "r"(a[3]), "r"(b0), "r"(b1));
}
__device__ __forceinline__ void stcg2(void* p, uint32_t a, uint32_t b) {
    asm volatile("st.global.cg.v2.b32 [%0], {%1,%2};" :: "l"(p), "r"(a), "r"(b));
}
__device__ __forceinline__ void stcg16(void* p, unsigned short v) {
    asm volatile("st.global.cg.u16 [%0], %1;" :: "l"(p), "h"(v));
}

__device__ __forceinline__ float sigm(float x) { return 1.0f / (1.0f + __expf(-x)); }

__device__ __forceinline__ void b2split(float v, unsigned short& hi, unsigned short& lo) {
    __nv_bfloat16 h = __float2bfloat16_rn(v);
    float r = v - __bfloat162float(h);
    __nv_bfloat16 l2 = __float2bfloat16_rn(r);
    hi = __bfloat16_as_ushort(h);
    lo = __bfloat16_as_ushort(l2);
}

// ---- A chunk staging: 128m x 64k, hi+lo, SW128 swizzle ---------------------
__device__ __forceinline__ void stage_chunk(
    const __nv_bfloat16* s0h, const __nv_bfloat16* s0l,
    const __nv_bfloat16* s1h, const __nv_bfloat16* s1l,
    int c, uint32_t dstbase)
{
    const __nv_bfloat16* ph = (c < 8) ? s0h : s1h;
    const __nv_bfloat16* pl = (c < 8) ? s0l : s1l;
    int coff = (c & 7) << 6;
    int tr = threadIdx.x >> 3, gr = threadIdx.x & 7;
#pragma unroll
    for (int jj = 0; jj < 8; ++jj) {
        int row = jj * 16 + tr;
        uint32_t d = dstbase + row * 128 + ((gr ^ (row & 7)) << 4);
        const char* gh = (const char*)(ph + (size_t)row * 512 + coff) + (gr << 4);
        const char* gl = (const char*)(pl + (size_t)row * 512 + coff) + (gr << 4);
        cp16(d, gh);
        cp16(d + 16384, gl);
    }
}

// ---- one layer phase -------------------------------------------------------
__device__ __forceinline__ void phase(
    int l, int t, int blk,
    const __nv_bfloat16* s0h, const __nv_bfloat16* s0l,
    const __nv_bfloat16* s1h, const __nv_bfloat16* s1l,
    __nv_bfloat16* hdsth, __nv_bfloat16* hdstl,
    __nv_bfloat16* mdsth, __nv_bfloat16* mdstl,   // layer-0 only, else null
    char* sm, uint32_t smb,
    float (&creg)[4],
    const float* __restrict__ masks, float* __restrict__ out)
{
    int tid = threadIdx.x, wid = tid >> 5, lam = tid & 31;
    int sub = lam >> 3, lrow = lam & 7;
    const uint2* bf = (const uint2*)(sm + SM_W);

    float acc[2][2][4] = {};

    stage_chunk(s0h, s0l, s1h, s1l, 0, smb + SM_A);
    cp_commit();
    stage_chunk(s0h, s0l, s1h, s1l, 1, smb + SM_A + 32768);
    cp_commit();

#pragma unroll 1
    for (int c = 0; c < 16; ++c) {
        if (c < 15) cp_wait<1>(); else cp_wait<0>();
        __syncthreads();
        uint32_t abase = smb + SM_A + (c & 1) * 32768;
#pragma unroll
        for (int ks = 0; ks < 4; ++ks) {
            uint32_t Ah[2][4], Al[2][4];
#pragma unroll
            for (int mt = 0; mt < 2; ++mt) {
                int r = wid * 32 + mt * 16 + ((sub & 1) << 3) + lrow;
                uint32_t aoff = r * 128 + (((2 * ks + (sub >> 1)) ^ (r & 7)) << 4);
                ldm4(Ah[mt], abase + aoff);
                ldm4(Al[mt], abase + 16384 + aoff);
            }
            int sg = c * 4 + ks;
            uint2 Bh0 = bf[(((l * 2 + 0) * 64 + sg) * 2 + 0) * 32 + lam];
            uint2 Bh1 = bf[(((l * 2 + 0) * 64 + sg) * 2 + 1) * 32 + lam];
            uint2 Bl0 = bf[(((l * 2 + 1) * 64 + sg) * 2 + 0) * 32 + lam];
            uint2 Bl1 = bf[(((l * 2 + 1) * 64 + sg) * 2 + 1) * 32 + lam];
#pragma unroll
            for (int mt = 0; mt < 2; ++mt) {
                mma(acc[mt][0], Ah[mt], Bh0.x, Bh0.y);
                mma(acc[mt][1], Ah[mt], Bh1.x, Bh1.y);
                mma(acc[mt][0], Ah[mt], Bl0.x, Bl0.y);
                mma(acc[mt][1], Ah[mt], Bl1.x, Bl1.y);
                mma(acc[mt][0], Al[mt], Bh0.x, Bh0.y);
                mma(acc[mt][1], Al[mt], Bh1.x, Bh1.y);
            }
        }
        __syncthreads();
        if (c < 14) {
            stage_chunk(s0h, s0l, s1h, s1l, c + 2, smb + SM_A + (c & 1) * 32768);
            cp_commit();
        }
    }

    // z -> smem
    float* zsh = (float*)(sm + SM_ZSH);
#pragma unroll
    for (int mt = 0; mt < 2; ++mt)
#pragma unroll
        for (int nt = 0; nt < 2; ++nt) {
            int m0 = wid * 32 + mt * 16 + (lam >> 2);
            int n0 = nt * 8 + (lam & 3) * 2;
            zsh[n0 * 132 + m0]           = acc[mt][nt][0];
            zsh[(n0 + 1) * 132 + m0]     = acc[mt][nt][1];
            zsh[n0 * 132 + m0 + 8]       = acc[mt][nt][2];
            zsh[(n0 + 1) * 132 + m0 + 8] = acc[mt][nt][3];
        }
    __syncthreads();

    // gates: thread = batch row n, 4 units
    int n = tid;
    float m  = __ldg(masks + t * 128 + n);
    float mn = (t < TSTEPS - 1) ? __ldg(masks + (t + 1) * 128 + n) : 0.f;
    const float* bs = (const float*)(sm + SM_BIAS) + l * 16;
    unsigned short sh[4], sl[4], th[4], tl[4];
    float hv[4];
#pragma unroll
    for (int u = 0; u < 4; ++u) {
        float zi = zsh[(0  + u) * 132 + n] + bs[u];
        float zf = zsh[(4  + u) * 132 + n] + bs[4 + u];
        float zg = zsh[(8  + u) * 132 + n] + bs[8 + u];
        float zo = zsh[(12 + u) * 132 + n] + bs[12 + u];
        float ii = sigm(zi), ff = sigm(zf), oo = sigm(zo);
        float gg = tanhf(zg);
        float cc = ff * (creg[u] * m) + ii * gg;
        float hh = oo * tanhf(cc);
        creg[u] = cc;
        hv[u] = hh;
        b2split(hh * mn, sh[u], sl[u]);          // next-step state, pre-masked
        if (l == 0) b2split(hh, th[u], tl[u]);   // layer-1 input, unmasked
    }
    size_t base = (size_t)n * 512 + blk * 4;
    stcg2(hdsth + base, sh[0] | ((uint32_t)sh[1] << 16), sh[2] | ((uint32_t)sh[3] << 16));
    stcg2(hdstl + base, sl[0] | ((uint32_t)sl[1] << 16), sl[2] | ((uint32_t)sl[3] << 16));
    if (l == 0) {
        stcg2(mdsth + base, th[0] | ((uint32_t)th[1] << 16), th[2] | ((uint32_t)th[3] << 16));
        stcg2(mdstl + base, tl[0] | ((uint32_t)tl[1] << 16), tl[2] | ((uint32_t)tl[3] << 16));
    } else {
        *(float4*)(out + (size_t)t * 65536 + base) = make_float4(hv[0], hv[1], hv[2], hv[3]);
    }
    if (t == TSTEPS - 1) {
#pragma unroll
        for (int u = 0; u < 4; ++u) {
            out[OUTN + l * 131072 + n * 1024 + blk * 4 + u]       = hv[u];
            out[OUTN + l * 131072 + n * 1024 + 512 + blk * 4 + u] = creg[u];
        }
    }
}

// ---- main persistent kernel ------------------------------------------------
__global__ void __launch_bounds__(NTHR, 1) lstm_tc(
    const float* __restrict__ hxs, const float* __restrict__ masks,
    const float* __restrict__ W_ih, const float* __restrict__ W_hh,
    const float* __restrict__ b_ih, const float* __restrict__ b_hh,
    float* __restrict__ out)
{
    extern __shared__ __align__(1024) char sm[];
    uint32_t smb = (uint32_t)__cvta_generic_to_shared(sm);
    int tid = threadIdx.x, blk = blockIdx.x;

    // weight conversion -> B-fragment layout (hi & lo)
    unsigned short* bw = (unsigned short*)(sm + SM_W);
    for (int idx = tid; idx < 2 * 16 * 1024; idx += NTHR) {
        int l = idx >> 14, col = (idx >> 10) & 15, k = idx & 1023;
        int grow = (col >> 2) * 512 + blk * 4 + (col & 3);
        float w = (k < 512)
            ? W_ih[((size_t)l * 2048 + grow) * 512 + k]
            : W_hh[((size_t)l * 2048 + grow) * 512 + (k - 512)];
        unsigned short hi, lo;
        b2split(w, hi, lo);
        int s = k >> 4, kk = k & 15;
        int reg = (kk >> 3) & 1, pos = kk & 1;
        int lamd = (col & 7) * 4 + ((kk & 7) >> 1);
        int nt = col >> 3;
        int base = (((l * 2 + 0) * 64 + s) * 2 + nt) * 128 + lamd * 4 + reg * 2 + pos;
        bw[base] = hi;
        bw[base + 64 * 2 * 128] = lo;   // half stride = 64ks*2nt*128
    }
    if (tid < 32) {
        int l = tid >> 4, c = tid & 15;
        int grow = (c >> 2) * 512 + blk * 4 + (c & 3);
        ((float*)(sm + SM_BIAS))[tid] = b_ih[l * 2048 + grow] + b_hh[l * 2048 + grow];
    }

    // init masked h state (pp=0) from hxs * masks[0]
    for (int idx = blk * NTHR + tid; idx < 2 * 65536; idx += NBLK * NTHR) {
        int l = idx >> 16, r = idx & 65535;
        int n = r >> 9, j = r & 511;
        float v = hxs[(size_t)l * 131072 + n * 1024 + j] * __ldg(masks + n);
        unsigned short hi, lo;
        b2split(v, hi, lo);
        stcg16(&g_hst[l][0][0][r], hi);
        stcg16(&g_hst[l][0][1][r], lo);
    }
    // init c in registers
    float creg[2][4];
#pragma unroll
    for (int l = 0; l < 2; ++l)
#pragma unroll
        for (int u = 0; u < 4; ++u)
            creg[l][u] = hxs[(size_t)l * 131072 + tid * 1024 + 512 + blk * 4 + u];

    grid_barrier();

#pragma unroll 1
    for (int t = 0; t < TSTEPS; ++t) {
        int pr = t & 1, pw = pr ^ 1, mb = t & 1;
        // layer 0: A = [x_t ; masked h0_prev]
        phase(0, t, blk,
              g_x_hi + (size_t)t * 65536, g_x_lo + (size_t)t * 65536,
              g_hst[0][pr][0], g_hst[0][pr][1],
              g_hst[0][pw][0], g_hst[0][pw][1],
              g_mid[mb][0], g_mid[mb][1],
              sm, smb, creg[0], masks, out);
        grid_barrier();
        // layer 1: A = [h0_new unmasked ; masked h1_prev]
        phase(1, t, blk,
              g_mid[mb][0], g_mid[mb][1],
              g_hst[1][pr][0], g_hst[1][pr][1],
              g_hst[1][pw][0], g_hst[1][pw][1],
              nullptr, nullptr,
              sm, smb, creg[1], masks, out);
    }
}

// ---- x -> bf16 hi/lo -------------------------------------------------------
__global__ void __launch_bounds__(256) xconv(const float* __restrict__ x) {
    size_t i = (size_t)blockIdx.x * 256 + threadIdx.x;
    if (i >= (size_t)OUTN / 4) return;
    float4 v = __ldg(((const float4*)x) + i);
    unsigned short h[4], l2[4];
    b2split(v.x, h[0], l2[0]);
    b2split(v.y, h[1], l2[1]);
    b2split(v.z, h[2], l2[2]);
    b2split(v.w, h[3], l2[3]);
    *(uint2*)(g_x_hi + i * 4) = make_uint2(h[0]  | ((uint32_t)h[1]  << 16), h[2]  | ((uint32_t)h[3]  << 16));
    *(uint2*)(g_x_lo + i * 4) = make_uint2(l2[0] | ((uint32_t)l2[1] << 16), l2[2] | ((uint32_t)l2[3] << 16));
}

// ---- LayerNorm -------------------------------------------------------------
__global__ void __launch_bounds__(256) ln_kernel(float* __restrict__ out,
                                                 const float* __restrict__ gamma,
                                                 const float* __restrict__ beta)
{
    int lane = threadIdx.x & 31;
    int row  = blockIdx.x * 8 + (threadIdx.x >> 5);
    float* p = out + (size_t)row * 512;
    float4 v[4];
    float s = 0.f, sq = 0.f;
#pragma unroll
    for (int k = 0; k < 4; ++k) {
        v[k] = ((const float4*)p)[(k << 5) + lane];
        s += v[k].x + v[k].y + v[k].z + v[k].w;
        sq = fmaf(v[k].x, v[k].x, sq); sq = fmaf(v[k].y, v[k].y, sq);
        sq = fmaf(v[k].z, v[k].z, sq); sq = fmaf(v[k].w, v[k].w, sq);
    }
#pragma unroll
    for (int o = 16; o; o >>= 1) {
        s  += __shfl_xor_sync(0xffffffffu, s,  o);
        sq += __shfl_xor_sync(0xffffffffu, sq, o);
    }
    float mean = s * (1.0f / 512.0f);
    float inv  = rsqrtf(sq * (1.0f / 512.0f) - mean * mean + 1e-5f);
#pragma unroll
    for (int k = 0; k < 4; ++k) {
        float4 g = ((const float4*)gamma)[(k << 5) + lane];
        float4 b = ((const float4*)beta)[(k << 5) + lane];
        float4 r;
        r.x = (v[k].x - mean) * inv * g.x + b.x;
        r.y = (v[k].y - mean) * inv * g.y + b.y;
        r.z = (v[k].z - mean) * inv * g.z + b.z;
        r.w = (v[k].w - mean) * inv * g.w + b.w;
        ((float4*)p)[(k << 5) + lane] = r;
    }
}

// ---------------------------------------------------------------------------
extern "C" void kernel_launch(void* const* d_in, const int* in_sizes, int n_in,
                              void* d_out, int out_size) {
    const float* x     = (const float*)d_in[0];
    const float* hxs   = (const float*)d_in[1];
    const float* masks = (const float*)d_in[2];
    const float* W_ih  = (const float*)d_in[3];
    const float* W_hh  = (const float*)d_in[4];
    const float* b_ih  = (const float*)d_in[5];
    const float* b_hh  = (const float*)d_in[6];
    const float* gamma = (const float*)d_in[7];
    const float* beta  = (const float*)d_in[8];
    float* out = (float*)d_out;

    cudaFuncSetAttribute(lstm_tc, cudaFuncAttributeMaxDynamicSharedMemorySize, SM_TOT);

    xconv<<<(OUTN / 4 + 255) / 256, 256>>>(x);
    lstm_tc<<<NBLK, NTHR, SM_TOT>>>(hxs, masks, W_ih, W_hh, b_ih, b_hh, out);
    ln_kernel<<<65536 / 8, 256>>>(out, gamma, beta);
}